// round 7
// baseline (speedup 1.0000x reference)
#include <cuda_runtime.h>
#include <cstdint>
#include <cstddef>
#include <math.h>

// ---------------------------------------------------------------------------
// LSTM  I=256 H=512 O=10 B=64 T=2048  (fp32, f32x2 packed-FMA pipe)
// R6: k_rec redesign — cp.async.bulk h staging (kills 8192 LDG/SM/step),
//     8x16 warp tiles with pre-splatted W (LDS traffic /2), flag-array
//     chip barrier (kills ATOMG serialization). k_fc warp-per-output.
// ---------------------------------------------------------------------------

#define TSZ  2048
#define NCTA 128

typedef unsigned long long ull;

// scratch (__device__ globals are the sanctioned scratch mechanism)
__device__ float    g_xg[268435456];     // 1 GiB: [T][4H][B]  (2048*2048*64)
__device__ float    g_h[2 * 512 * 64];   // double-buffered h: [H][B]
__device__ float    g_bias[2048];        // b_ih + b_hh
__device__ unsigned g_flags[NCTA];       // per-CTA step flags (chip barrier)

// ---- packed f32x2 helpers (Blackwell dual-fp32 pipe) ----------------------
__device__ __forceinline__ ull pk2(float a, float b) {
    ull r; asm("mov.b64 %0,{%1,%2};" : "=l"(r) : "f"(a), "f"(b)); return r;
}
__device__ __forceinline__ ull splat2(float a) {
    ull r; asm("mov.b64 %0,{%1,%1};" : "=l"(r) : "f"(a)); return r;
}
__device__ __forceinline__ void upk2(ull v, float& a, float& b) {
    asm("mov.b64 {%0,%1},%2;" : "=f"(a), "=f"(b) : "l"(v));
}
__device__ __forceinline__ ull fma2(ull a, ull b, ull c) {
    ull d; asm("fma.rn.f32x2 %0,%1,%2,%3;" : "=l"(d) : "l"(a), "l"(b), "l"(c));
    return d;
}

// ---- smem / mbarrier / bulk-copy helpers ----------------------------------
__device__ __forceinline__ uint32_t s2u(const void* p) {
    uint32_t a;
    asm("{ .reg .u64 t; cvta.to.shared.u64 t, %1; cvt.u32.u64 %0, t; }"
        : "=r"(a) : "l"(p));
    return a;
}
__device__ __forceinline__ void mbar_init(uint32_t m, unsigned cnt) {
    asm volatile("mbarrier.init.shared.b64 [%0], %1;" :: "r"(m), "r"(cnt) : "memory");
}
__device__ __forceinline__ void mbar_expect_tx(uint32_t m, unsigned bytes) {
    asm volatile("mbarrier.arrive.expect_tx.shared.b64 _, [%0], %1;"
                 :: "r"(m), "r"(bytes) : "memory");
}
__device__ __forceinline__ void mbar_wait(uint32_t m, int phase) {
    asm volatile(
        "{\n\t.reg .pred P;\n\t"
        "LW_%=:\n\t"
        "mbarrier.try_wait.parity.acquire.cta.shared::cta.b64 P, [%0], %1, 0x989680;\n\t"
        "@P bra LD_%=;\n\t"
        "bra LW_%=;\n\t"
        "LD_%=:\n\t}"
        :: "r"(m), "r"(phase) : "memory");
}
__device__ __forceinline__ void bulk_g2s(uint32_t dst, const void* src,
                                         unsigned bytes, uint32_t mbar) {
    asm volatile(
        "cp.async.bulk.shared::cluster.global.mbarrier::complete_tx::bytes "
        "[%0], [%1], %2, [%3];"
        :: "r"(dst), "l"(src), "r"(bytes), "r"(mbar) : "memory");
}

// ---------------------------------------------------------------------------
__global__ void k_init(const float* __restrict__ bih, const float* __restrict__ bhh) {
    int tid = blockIdx.x * blockDim.x + threadIdx.x;
    int nt  = gridDim.x * blockDim.x;
    if (tid < 2048) g_bias[tid] = bih[tid] + bhh[tid];
    for (int i = tid; i < 2 * 512 * 64; i += nt) g_h[i] = 0.0f;
    if (tid < NCTA) g_flags[tid] = 0u;
}

// ---------------------------------------------------------------------------
// Phase 1: xg[t][row][b] = sum_i W_ih[row][i] * x[b][t][i] + bias[row]
// (unchanged from R5 — passed)
// ---------------------------------------------------------------------------
__global__ void __launch_bounds__(256) k_inproj(const float* __restrict__ x,
                                                const float* __restrict__ Wih) {
    __shared__ __align__(16) float As[16 * 132];
    __shared__ __align__(16) float Bs[16 * 66];

    const int tid = threadIdx.x;
    const int bx  = blockIdx.x;
    const int t   = blockIdx.y;
    const int tr  = tid >> 4, tc = tid & 15;
    const int r0  = tr * 8,  c0 = tc * 4;
    const int kkg = tid & 3;
    const int bb  = tid >> 2;

    ull acc[8][2];
#pragma unroll
    for (int i = 0; i < 8; i++) { acc[i][0] = 0ull; acc[i][1] = 0ull; }

    for (int k0 = 0; k0 < 256; k0 += 16) {
#pragma unroll
        for (int j = 0; j < 2; j++) {
            int rr = (tid >> 2) + j * 64;
            float4 av = *(const float4*)(Wih + (size_t)(bx * 128 + rr) * 256 + k0 + kkg * 4);
            As[(kkg * 4 + 0) * 132 + rr] = av.x;
            As[(kkg * 4 + 1) * 132 + rr] = av.y;
            As[(kkg * 4 + 2) * 132 + rr] = av.z;
            As[(kkg * 4 + 3) * 132 + rr] = av.w;
        }
        {
            float4 bv = *(const float4*)(x + ((size_t)bb * 2048 + t) * 256 + k0 + kkg * 4);
            Bs[(kkg * 4 + 0) * 66 + bb] = bv.x;
            Bs[(kkg * 4 + 1) * 66 + bb] = bv.y;
            Bs[(kkg * 4 + 2) * 66 + bb] = bv.z;
            Bs[(kkg * 4 + 3) * 66 + bb] = bv.w;
        }
        __syncthreads();
#pragma unroll
        for (int k = 0; k < 16; k++) {
            float4 a0 = *(const float4*)&As[k * 132 + r0];
            float4 a1 = *(const float4*)&As[k * 132 + r0 + 4];
            ull b0 = *(const ull*)&Bs[k * 66 + c0];
            ull b1 = *(const ull*)&Bs[k * 66 + c0 + 2];
            ull sp;
            sp = splat2(a0.x); acc[0][0] = fma2(sp, b0, acc[0][0]); acc[0][1] = fma2(sp, b1, acc[0][1]);
            sp = splat2(a0.y); acc[1][0] = fma2(sp, b0, acc[1][0]); acc[1][1] = fma2(sp, b1, acc[1][1]);
            sp = splat2(a0.z); acc[2][0] = fma2(sp, b0, acc[2][0]); acc[2][1] = fma2(sp, b1, acc[2][1]);
            sp = splat2(a0.w); acc[3][0] = fma2(sp, b0, acc[3][0]); acc[3][1] = fma2(sp, b1, acc[3][1]);
            sp = splat2(a1.x); acc[4][0] = fma2(sp, b0, acc[4][0]); acc[4][1] = fma2(sp, b1, acc[4][1]);
            sp = splat2(a1.y); acc[5][0] = fma2(sp, b0, acc[5][0]); acc[5][1] = fma2(sp, b1, acc[5][1]);
            sp = splat2(a1.z); acc[6][0] = fma2(sp, b0, acc[6][0]); acc[6][1] = fma2(sp, b1, acc[6][1]);
            sp = splat2(a1.w); acc[7][0] = fma2(sp, b0, acc[7][0]); acc[7][1] = fma2(sp, b1, acc[7][1]);
        }
        __syncthreads();
    }
#pragma unroll
    for (int i = 0; i < 8; i++) {
        int row = bx * 128 + r0 + i;
        float bias = g_bias[row];
        float p0, p1, p2, p3;
        upk2(acc[i][0], p0, p1);
        upk2(acc[i][1], p2, p3);
        *(float4*)(g_xg + ((size_t)t * 2048 + row) * 64 + c0) =
            make_float4(p0 + bias, p1 + bias, p2 + bias, p3 + bias);
    }
}

// ---------------------------------------------------------------------------
// Phase 2: persistent recurrence, 128 CTAs x 256 threads.
// smem: Wt2 (512k x 16rows of pre-splatted {w,w} ull = 64KB)
//       hsh (2 x 32KB double-buffered h chunks, filled by cp.async.bulk)
//       gsh (16 x 64 gate pre-activations)
// Warp tile: 8 rows x 16 cols. Lane tile: 2 rows x 2 cols (2 ull accs).
// Per k per lane: LDS.128 (W splat pair) + LDS.64 (h pair) + 2 FFMA2.
// Chip barrier: per-CTA release flag + 128-thread acquire poll.
// ---------------------------------------------------------------------------
__global__ void __launch_bounds__(256, 1) k_rec(const float* __restrict__ Whh) {
    extern __shared__ __align__(16) float sm[];
    ull*   Wt2 = (ull*)sm;            // 8192 ull  = 64 KB
    float* hsh = sm + 16384;          // 16384 fl  = 64 KB (2 x 32KB)
    float* gsh = sm + 32768;          // 1024 fl   =  4 KB
    __shared__ __align__(8) ull mbars[2];

    const int tid  = threadIdx.x;
    const int h0   = blockIdx.x * 4;
    const int wid  = tid >> 5, lane = tid & 31;
    const int rg   = lane >> 3, cg = lane & 7;
    const int wrow = (wid & 1) * 8 + rg * 2;       // even local row
    const int c    = (wid >> 1) * 16 + cg * 2;     // even col
    const int grow0 = (wrow & 3) * 512 + h0 + (wrow >> 2); // global gate row
    // wrow even -> wrow+1 has same unit, next gate: grow1 = grow0 + 512

    const uint32_t mb0 = s2u(&mbars[0]);
    const uint32_t mb1 = s2u(&mbars[1]);
    const uint32_t hsh_u = s2u(hsh);

    // load W slab pre-splatted: Wt2[k*16 + rloc] = {w,w}, w = Whh[grow(rloc)][k]
#pragma unroll
    for (int j = 0; j < 8; j++) {
        int flat = tid + j * 256;          // 0..2047
        int rl = flat >> 7, k4 = flat & 127;
        int grw = (rl & 3) * 512 + h0 + (rl >> 2);
        float4 w4 = *(const float4*)(Whh + (size_t)grw * 512 + k4 * 4);
        Wt2[(k4 * 4 + 0) * 16 + rl] = splat2(w4.x);
        Wt2[(k4 * 4 + 1) * 16 + rl] = splat2(w4.y);
        Wt2[(k4 * 4 + 2) * 16 + rl] = splat2(w4.z);
        Wt2[(k4 * 4 + 3) * 16 + rl] = splat2(w4.w);
    }
    if (tid == 0) { mbar_init(mb0, 1u); mbar_init(mb1, 1u); }
    float cstate = 0.0f;                   // cell for (u2 = tid>>6, b = tid&63)
    int ph0 = 0, ph1 = 0;
    __syncthreads();

    for (int s = 0; s < TSZ; s++) {
        const float* hin  = g_h + (s & 1) * 32768;
        float*       hout = g_h + ((s + 1) & 1) * 32768;

        // acc init from xg (streaming)
        float2 x0 = __ldcs((const float2*)(g_xg + ((size_t)s * 2048 + grow0) * 64 + c));
        float2 x1 = __ldcs((const float2*)(g_xg + ((size_t)s * 2048 + grow0 + 512) * 64 + c));
        ull acc0 = pk2(x0.x, x0.y);
        ull acc1 = pk2(x1.x, x1.y);

        // kick off first two 32KB h chunks
        if (tid == 0) {
            asm volatile("fence.proxy.async;" ::: "memory");
            mbar_expect_tx(mb0, 32768u);
            bulk_g2s(hsh_u, hin, 32768u, mb0);
            mbar_expect_tx(mb1, 32768u);
            bulk_g2s(hsh_u + 32768u, hin + 8192, 32768u, mb1);
        }

#pragma unroll
        for (int kc = 0; kc < 4; kc++) {
            const int buf = kc & 1;
            if (buf == 0) { mbar_wait(mb0, ph0); ph0 ^= 1; }
            else          { mbar_wait(mb1, ph1); ph1 ^= 1; }

            const ull*   wp = Wt2 + (kc * 128) * 16 + wrow;
            const float* hp = hsh + buf * 8192 + c;
#pragma unroll 8
            for (int kl = 0; kl < 128; kl++) {
                ulonglong2 w = *(const ulonglong2*)(wp + kl * 16);
                ull h2 = *(const ull*)(hp + kl * 64);
                acc0 = fma2(w.x, h2, acc0);
                acc1 = fma2(w.y, h2, acc1);
            }
            __syncthreads();     // all consumers done with buf
            if (kc < 2 && tid == 0) {
                const uint32_t m = buf ? mb1 : mb0;
                mbar_expect_tx(m, 32768u);
                bulk_g2s(hsh_u + buf * 32768u, hin + (kc + 2) * 8192, 32768u, m);
            }
        }

        // publish gate pre-activations
        *(ull*)(gsh + wrow * 64 + c)       = acc0;
        *(ull*)(gsh + (wrow + 1) * 64 + c) = acc1;
        __syncthreads();

        // cell update: one cell per thread
        {
            int u2 = tid >> 6, b = tid & 63;
            float ig = gsh[(u2 * 4 + 0) * 64 + b];
            float fg = gsh[(u2 * 4 + 1) * 64 + b];
            float gg = gsh[(u2 * 4 + 2) * 64 + b];
            float og = gsh[(u2 * 4 + 3) * 64 + b];
            ig = 1.0f / (1.0f + expf(-ig));
            fg = 1.0f / (1.0f + expf(-fg));
            gg = tanhf(gg);
            og = 1.0f / (1.0f + expf(-og));
            cstate = fg * cstate + ig * gg;
            hout[(h0 + u2) * 64 + b] = og * tanhf(cstate);
        }
        __syncthreads();                       // all hout STGs done (CTA view)

        // chip barrier: release own flag, acquire all 128 flags
        if (tid == 0) {
            asm volatile("st.global.release.gpu.u32 [%0], %1;"
                         :: "l"(&g_flags[blockIdx.x]), "r"(s + 1) : "memory");
        }
        if (tid < NCTA) {
            unsigned v;
            do {
                asm volatile("ld.global.acquire.gpu.u32 %0, [%1];"
                             : "=r"(v) : "l"(&g_flags[tid]) : "memory");
            } while (v < (unsigned)(s + 1));
        }
        __syncthreads();
    }
}

// ---------------------------------------------------------------------------
// FC head: out[b][o] = sum_h h_last[h][b] * W_fc[o][h] + b_fc[o]
// warp-per-output: 640 warps = 80 blocks x 8 warps, shfl reduction.
// ---------------------------------------------------------------------------
__global__ void __launch_bounds__(256) k_fc(const float* __restrict__ Wfc,
                                            const float* __restrict__ bfc,
                                            float* __restrict__ out) {
    int g    = blockIdx.x * 8 + (threadIdx.x >> 5);   // 0..639
    int lane = threadIdx.x & 31;
    int o = g >> 6, b = g & 63;
    float s = 0.0f;
#pragma unroll
    for (int j = 0; j < 16; j++) {
        int h = lane + j * 32;
        s += g_h[h * 64 + b] * Wfc[o * 512 + h];
    }
#pragma unroll
    for (int m = 16; m > 0; m >>= 1)
        s += __shfl_xor_sync(0xFFFFFFFFu, s, m);
    if (lane == 0) out[b * 10 + o] = s + bfc[o];
}

// ---------------------------------------------------------------------------
extern "C" void kernel_launch(void* const* d_in, const int* in_sizes, int n_in,
                              void* d_out, int out_size) {
    const float* x    = (const float*)d_in[0];
    const float* W_ih = (const float*)d_in[1];
    const float* W_hh = (const float*)d_in[2];
    const float* b_ih = (const float*)d_in[3];
    const float* b_hh = (const float*)d_in[4];
    const float* W_fc = (const float*)d_in[5];
    const float* b_fc = (const float*)d_in[6];
    float* out = (float*)d_out;

    const int SMEM_REC = (16384 + 16384 + 1024) * 4;   // 132 KB dynamic
    cudaFuncSetAttribute(k_rec, cudaFuncAttributeMaxDynamicSharedMemorySize, SMEM_REC);

    k_init<<<64, 256>>>(b_ih, b_hh);
    k_inproj<<<dim3(16, 2048), 256>>>(x, W_ih);
    k_rec<<<NCTA, 256, SMEM_REC>>>(W_hh);
    k_fc<<<80, 256>>>(W_fc, b_fc, out);
}